// round 9
// baseline (speedup 1.0000x reference)
#include <cuda_runtime.h>

// RNN: B=4096, T=1024, H=64, scalar input, C=5 head.
//   h_{t+1}[b,i] = tanh(x[b,t]*w_ih[i] + b_ih[i] + b_hh[i] + sum_j h_t[b,j]*w_hh[i,j])
//   out[b,c]     = sum_j hT[b,j]*w_head[c,j] + b_head[c]
//
// R8: j-split warp pairs, 4 warps/SMSP (512 threads, 16 warps, 8 pairs).
// Pair p owns 4 batches. Half-A accumulates j in [0,32), half-B j in [32,64):
// h is still read ONCE per owning pair (no R6-style traffic doubling).
// Lane l owns adjacent rows {2l, 2l+1} -> W_hh half-row pair = 64 regs.
// Partial f32x2 accumulators exchanged via coalesced SMEM; each half
// finalizes 2 of the 4 batches (add + hadd + tanh + paired store).
// Two 64-thread named barriers per step per pair; pairs independent.

#define BB 4096
#define TT 1024
#define HH 64
#define CC 5
#define NB 32            // batches per CTA
#define NTHREADS 512     // 16 warps, 8 pairs
#define BPP 4            // batches per pair

typedef unsigned long long u64;

__device__ __forceinline__ u64 pk2(float lo, float hi) {
    u64 r; asm("mov.b64 %0, {%1,%2};" : "=l"(r) : "f"(lo), "f"(hi)); return r;
}
__device__ __forceinline__ float2 up2(u64 v) {
    float2 f; asm("mov.b64 {%0,%1}, %2;" : "=f"(f.x), "=f"(f.y) : "l"(v)); return f;
}
__device__ __forceinline__ u64 fma2(u64 a, u64 b, u64 c) {
    u64 d; asm("fma.rn.f32x2 %0, %1, %2, %3;" : "=l"(d) : "l"(a), "l"(b), "l"(c)); return d;
}
__device__ __forceinline__ u64 add2(u64 a, u64 b) {
    u64 d; asm("add.rn.f32x2 %0, %1, %2;" : "=l"(d) : "l"(a), "l"(b)); return d;
}
__device__ __forceinline__ float ftanh(float xv) {
    // tanh(x) = 1 - 2/(e^{2x}+1); exact at saturation via inf.
    float e = __expf(2.0f * xv);
    return 1.0f - __fdividef(2.0f, e + 1.0f);
}
__device__ __forceinline__ void bar_pair(int id) {
    asm volatile("bar.sync %0, 64;" :: "r"(id) : "memory");
}

extern "C" __global__ void __launch_bounds__(NTHREADS, 1)
rnn_jsplit_kernel(const float* __restrict__ x,
                  const float* __restrict__ w_ih,
                  const float* __restrict__ b_ih,
                  const float* __restrict__ w_hh,
                  const float* __restrict__ b_hh,
                  const float* __restrict__ w_head,
                  const float* __restrict__ b_head,
                  float* __restrict__ out)
{
    __shared__ __align__(16) float      hs[2][NB][HH];     // 16 KB, h double-buffer
    __shared__ __align__(16) ulonglong2 ex[2][8][2][32];   // 16 KB, partial exchange
                                                           // [idx][pair][half][lane]
    const int tid  = threadIdx.x;
    const int lane = tid & 31;
    const int wrp  = tid >> 5;
    const int pair = wrp >> 1;              // 0..7
    const int half = wrp & 1;               // 0: j 0..31, 1: j 32..63
    const int b0   = pair * BPP;            // pair's local batch base
    const int fb   = b0 + half * 2;         // this half finalizes fb, fb+1
    const int gbf  = blockIdx.x * NB + fb;  // global finalize batch base
    const int r0   = 2 * lane;              // rows r0, r0+1 (adjacent)
    const int sb   = half ? 0 : 2;          // batches (rel) whose accs we ship

    // --- W_hh rows {r0, r0+1}, this half's 32 j's, as j-pair u64 (64 regs) ---
    u64 wreg[2][16];
#pragma unroll
    for (int r = 0; r < 2; r++) {
        const u64* wr = (const u64*)(w_hh + (size_t)(r0 + r) * HH + half * 32);
#pragma unroll
        for (int jp = 0; jp < 16; jp++) wreg[r][jp] = wr[jp];
    }
    // w_ih / bias for this lane's row pair (for finalize)
    const u64 whp = pk2(w_ih[r0], w_ih[r0 + 1]);
    const u64 bip = pk2(b_ih[r0] + b_hh[r0], b_ih[r0 + 1] + b_hh[r0 + 1]);

    // --- zero h buffer 0 ---
    for (int e = tid; e < NB * HH; e += NTHREADS) ((float*)hs[0])[e] = 0.0f;

    // --- x chunks for finalize batches; prefetch 32 steps ahead ---
    float xcur[2], xnxt[2];
#pragma unroll
    for (int k = 0; k < 2; k++) xnxt[k] = x[(size_t)(gbf + k) * TT + lane];

    __syncthreads();

    // --- per-pair skew preamble to seed anti-phase across pairs ---
    {
        int links = (pair & 3) * 96;          // 0 / ~384 / ~768 / ~1152 cyc
        float z = up2(bip).x + 1.0f;
        for (int i = 0; i < links; i++)
            asm volatile("fma.rn.f32 %0, %0, %1, %2;"
                         : "+f"(z) : "f"(0.9999999f), "f"(1e-30f));
        if (z == -123456.75f) ((float*)hs[0])[0] = z;   // defeat DCE, never true
    }

    int cur = 0;
    for (int t = 0; t < TT; t++) {
        const int tc = t & 31;
        if (tc == 0) {
            xcur[0] = xnxt[0]; xcur[1] = xnxt[1];
            if (t + 32 < TT) {
#pragma unroll
                for (int k = 0; k < 2; k++)
                    xnxt[k] = x[(size_t)(gbf + k) * TT + (t + 32) + lane];
            }
        }

        const float* hc = (const float*)hs[cur];
        const ulonglong2* hq0 = (const ulonglong2*)(hc + (b0 + 0) * HH + half * 32);
        const ulonglong2* hq1 = (const ulonglong2*)(hc + (b0 + 1) * HH + half * 32);
        const ulonglong2* hq2 = (const ulonglong2*)(hc + (b0 + 2) * HH + half * 32);
        const ulonglong2* hq3 = (const ulonglong2*)(hc + (b0 + 3) * HH + half * 32);

        u64 acc[2][4];
#pragma unroll
        for (int r = 0; r < 2; r++)
#pragma unroll
            for (int k = 0; k < 4; k++) acc[r][k] = 0ull;

#pragma unroll
        for (int q = 0; q < 8; q++) {        // 4 local j's per iter
            ulonglong2 h0 = hq0[q];          // broadcast loads
            ulonglong2 h1 = hq1[q];
            ulonglong2 h2 = hq2[q];
            ulonglong2 h3 = hq3[q];
#pragma unroll
            for (int r = 0; r < 2; r++) {
                const u64 wa = wreg[r][2 * q], wb = wreg[r][2 * q + 1];
                acc[r][0] = fma2(wa, h0.x, acc[r][0]);
                acc[r][1] = fma2(wa, h1.x, acc[r][1]);
                acc[r][2] = fma2(wa, h2.x, acc[r][2]);
                acc[r][3] = fma2(wa, h3.x, acc[r][3]);
                acc[r][0] = fma2(wb, h0.y, acc[r][0]);
                acc[r][1] = fma2(wb, h1.y, acc[r][1]);
                acc[r][2] = fma2(wb, h2.y, acc[r][2]);
                acc[r][3] = fma2(wb, h3.y, acc[r][3]);
            }
        }

        // ship partial accs for the batches the partner finalizes (coalesced)
        ex[0][pair][half][lane] = make_ulonglong2(acc[0][sb], acc[0][sb + 1]);
        ex[1][pair][half][lane] = make_ulonglong2(acc[1][sb], acc[1][sb + 1]);
        bar_pair(pair);
        const ulonglong2 p0 = ex[0][pair][half ^ 1][lane];  // partner acc row r0
        const ulonglong2 p1 = ex[1][pair][half ^ 1][lane];  // partner acc row r0+1

        // finalize 2 batches: add partner partial, hadd, +base, tanh, store pair
        float* hn = (float*)hs[cur ^ 1];
        const int fr = half * 2;             // rel index of finalize batches
#pragma unroll
        for (int k = 0; k < 2; k++) {
            float xv = __shfl_sync(0xffffffffu, xcur[k], tc);
            u64 basep = fma2(pk2(xv, xv), whp, bip);      // {base r0, base r0+1}
            u64 s0 = add2(acc[0][fr + k], k ? p0.y : p0.x);
            u64 s1 = add2(acc[1][fr + k], k ? p1.y : p1.x);
            float2 bb = up2(basep);
            float2 a0 = up2(s0);
            float2 a1 = up2(s1);
            float v0 = ftanh(a0.x + a0.y + bb.x);
            float v1 = ftanh(a1.x + a1.y + bb.y);
            *(u64*)&hn[(fb + k) * HH + r0] = pk2(v0, v1); // adjacent rows
        }
        bar_pair(pair);
        cur ^= 1;
    }

    // --- head: out[b,c] = sum_j h[b,j]*w_head[c,j] + b_head[c] ---
    // half-0 warp of each pair: lanes 0..19 -> (batch k, class c)
    if (half == 0 && lane < BPP * CC) {
        const int k = lane / CC;
        const int c = lane % CC;
        const float* hf = hs[cur][b0 + k];
        float s = b_head[c];
#pragma unroll
        for (int j = 0; j < HH; j++)
            s = fmaf(hf[j], w_head[c * HH + j], s);
        out[(size_t)(blockIdx.x * NB + b0 + k) * CC + c] = s;
    }
}

extern "C" void kernel_launch(void* const* d_in, const int* in_sizes, int n_in,
                              void* d_out, int out_size)
{
    (void)in_sizes; (void)n_in; (void)out_size;
    const float* x      = (const float*)d_in[0];
    const float* w_ih   = (const float*)d_in[1];
    const float* b_ih   = (const float*)d_in[2];
    const float* w_hh   = (const float*)d_in[3];
    const float* b_hh   = (const float*)d_in[4];
    const float* w_head = (const float*)d_in[5];
    const float* b_head = (const float*)d_in[6];
    float* out = (float*)d_out;

    rnn_jsplit_kernel<<<BB / NB, NTHREADS>>>(
        x, w_ih, b_ih, w_hh, b_hh, w_head, b_head, out);
}

// round 11
// speedup vs baseline: 1.7533x; 1.7533x over previous
#include <cuda_runtime.h>
#include <cuda_bf16.h>
#include <cstdint>

// RNN: B=4096, T=1024, H=64, scalar input, C=5 head.
//   h_{t+1}[b,i] = tanh(x[b,t]*w_ih[i] + b_ih[i] + b_hh[i] + sum_j h_t[b,j]*w_hh[i,j])
//   out[b,c]     = sum_j hT[b,j]*w_head[c,j] + b_head[c]
//
// R10: mma.sync (HMMA, sm_80+ PTX -- compiles at plain sm_100) bf16-split
// recurrence. A = H[32 x 64] (batches x j) via ldmatrix from SMEM, B = W^T
// in loop-invariant register fragments. 3 products (Whi*Hhi + Whi*Hlo +
// Wlo*Hhi), fp32 accumulators in registers. 8 warps: warp w -> batch-half
// (w>>2), N-tiles {2*(w&3), 2*(w&3)+1}. h stored as bf16 hi/lo arrays with
// 144B row stride (conflict-free ldmatrix). One __syncthreads per step.

#define BB 4096
#define TT 1024
#define HH 64
#define CC 5
#define NB 32
#define NTHREADS 256
#define HSTR 72            // bf16 elems per h row = 144 B

typedef uint32_t u32;

__device__ __forceinline__ u32 smem_u32(const void* p) {
    u32 a;
    asm("{ .reg .u64 t; cvta.to.shared.u64 t, %1; cvt.u32.u64 %0, t; }"
        : "=r"(a) : "l"(p));
    return a;
}
__device__ __forceinline__ u32 pkbf(float a, float b) {
    __nv_bfloat162 t = __floats2bfloat162_rn(a, b);
    return *reinterpret_cast<u32*>(&t);
}
__device__ __forceinline__ float ftanh(float xv) {
    // tanh(x) = 1 - 2/(e^{2x}+1); exact at saturation via inf.
    float e = __expf(2.0f * xv);
    return 1.0f - __fdividef(2.0f, e + 1.0f);
}
__device__ __forceinline__ void ldm4(u32* r, u32 addr) {
    asm volatile("ldmatrix.sync.aligned.m8n8.x4.shared.b16 {%0,%1,%2,%3}, [%4];"
                 : "=r"(r[0]), "=r"(r[1]), "=r"(r[2]), "=r"(r[3]) : "r"(addr));
}
__device__ __forceinline__ void mma16816(float* d, const u32* a, const u32* b) {
    asm volatile(
        "mma.sync.aligned.m16n8k16.row.col.f32.bf16.bf16.f32 "
        "{%0,%1,%2,%3}, {%4,%5,%6,%7}, {%8,%9}, {%0,%1,%2,%3};"
        : "+f"(d[0]), "+f"(d[1]), "+f"(d[2]), "+f"(d[3])
        : "r"(a[0]), "r"(a[1]), "r"(a[2]), "r"(a[3]), "r"(b[0]), "r"(b[1]));
}

extern "C" __global__ void __launch_bounds__(NTHREADS, 1)
rnn_hmma_kernel(const float* __restrict__ x,
                const float* __restrict__ w_ih,
                const float* __restrict__ b_ih,
                const float* __restrict__ w_hh,
                const float* __restrict__ b_hh,
                const float* __restrict__ w_head,
                const float* __restrict__ b_head,
                float* __restrict__ out)
{
    __shared__ __align__(16) __nv_bfloat16 hhi[2][NB][HSTR];  // 9216 B
    __shared__ __align__(16) __nv_bfloat16 hlo[2][NB][HSTR];  // 9216 B
    __shared__ float xs[32][NB];                              // 4096 B
    __shared__ float hsfin[NB][HH];                           // 8192 B

    const int tid  = threadIdx.x;
    const int lane = tid & 31;
    const int wrp  = tid >> 5;
    const int nt2  = wrp & 3;           // N-tile pair: i in [nt2*16, nt2*16+16)
    const int mt   = wrp >> 2;          // batch half: batches [mt*16, mt*16+16)
    const int gb0  = blockIdx.x * NB;
    const int tig  = lane & 3;          // thread-in-group
    const int gid  = lane >> 2;         // group id

    // --- B fragments (W^T), loop-invariant, bf16 hi/lo split ---
    // b-frag lane mapping (m16n8k16 .col): n = gid, k = 2*tig(+1), reg1 k+8.
    u32 bhi[2][4][2], blo[2][4][2];
#pragma unroll
    for (int nt = 0; nt < 2; nt++) {
        const int i = nt2 * 16 + nt * 8 + gid;
        const float* wr = w_hh + (size_t)i * HH;
#pragma unroll
        for (int ks = 0; ks < 4; ks++) {
            int j0 = ks * 16 + 2 * tig;
            float w0 = wr[j0],     w1 = wr[j0 + 1];
            float w2 = wr[j0 + 8], w3 = wr[j0 + 9];
            float h0 = __bfloat162float(__float2bfloat16(w0));
            float h1 = __bfloat162float(__float2bfloat16(w1));
            float h2 = __bfloat162float(__float2bfloat16(w2));
            float h3 = __bfloat162float(__float2bfloat16(w3));
            bhi[nt][ks][0] = pkbf(w0, w1);
            bhi[nt][ks][1] = pkbf(w2, w3);
            blo[nt][ks][0] = pkbf(w0 - h0, w1 - h1);
            blo[nt][ks][1] = pkbf(w2 - h2, w3 - h3);
        }
    }

    // --- per-lane epilogue constants: i = ntbase + 2*tig + c ---
    float wihv[2][2], biasv[2][2];
#pragma unroll
    for (int nt = 0; nt < 2; nt++)
#pragma unroll
        for (int c = 0; c < 2; c++) {
            int i = nt2 * 16 + nt * 8 + 2 * tig + c;
            wihv[nt][c]  = w_ih[i];
            biasv[nt][c] = b_ih[i] + b_hh[i];
        }

    // --- zero h buffer 0 (both arrays) ---
    for (int e = tid; e < NB * HSTR / 2; e += NTHREADS) {
        ((u32*)hhi[0])[e] = 0u;
        ((u32*)hlo[0])[e] = 0u;
    }
    // --- stage x chunk 0 ---
    for (int e = tid; e < NB * 32; e += NTHREADS) {
        int b = e >> 5, tcc = e & 31;
        xs[tcc][b] = x[(size_t)(gb0 + b) * TT + tcc];
    }

    // --- ldmatrix lane address offset (A tile rows = batches of half mt) ---
    const u32 hhi_a = smem_u32(hhi);
    const u32 hlo_a = smem_u32(hlo);
    const u32 aoff  = (u32)((mt * 16 + (lane & 15)) * 144 + ((lane >> 4) & 1) * 16);

    const int br0 = mt * 16 + gid;      // this lane's epilogue batches
    const int br1 = br0 + 8;

    __syncthreads();

    int cur = 0;
    for (int t = 0; t < TT; t++) {
        const int tc = t & 31;
        if (tc == 0 && t > 0) {
            for (int e = tid; e < NB * 32; e += NTHREADS) {
                int b = e >> 5, tcc = e & 31;
                xs[tcc][b] = x[(size_t)(gb0 + b) * TT + t + tcc];
            }
            __syncthreads();
        }

        const u32 bufo = (u32)cur * (NB * HSTR * 2);

        // 6 independent depth-4 HMMA chains
        float dA[2][4] = {}, dB[2][4] = {}, dC[2][4] = {};
#pragma unroll
        for (int ks = 0; ks < 4; ks++) {
            u32 ahi[4], alo[4];
            ldm4(ahi, hhi_a + bufo + aoff + ks * 32);
            ldm4(alo, hlo_a + bufo + aoff + ks * 32);
            mma16816(dA[0], ahi, bhi[0][ks]);
            mma16816(dA[1], ahi, bhi[1][ks]);
            mma16816(dB[0], alo, bhi[0][ks]);
            mma16816(dB[1], alo, bhi[1][ks]);
            mma16816(dC[0], ahi, blo[0][ks]);
            mma16816(dC[1], ahi, blo[1][ks]);
        }

        // epilogue: combine, +x*w_ih+bias, tanh, split to bf16 hi/lo, store
        const float xv0 = xs[tc][br0];
        const float xv1 = xs[tc][br1];
        const int nxt = cur ^ 1;
#pragma unroll
        for (int nt = 0; nt < 2; nt++) {
            const int ic = nt2 * 16 + nt * 8 + 2 * tig;
            float s0 = dA[nt][0] + dB[nt][0] + dC[nt][0] + fmaf(xv0, wihv[nt][0], biasv[nt][0]);
            float s1 = dA[nt][1] + dB[nt][1] + dC[nt][1] + fmaf(xv0, wihv[nt][1], biasv[nt][1]);
            float s2 = dA[nt][2] + dB[nt][2] + dC[nt][2] + fmaf(xv1, wihv[nt][0], biasv[nt][0]);
            float s3 = dA[nt][3] + dB[nt][3] + dC[nt][3] + fmaf(xv1, wihv[nt][1], biasv[nt][1]);
            float v0 = ftanh(s0), v1 = ftanh(s1), v2 = ftanh(s2), v3 = ftanh(s3);
            *(u32*)&hhi[nxt][br0][ic] = pkbf(v0, v1);
            *(u32*)&hhi[nxt][br1][ic] = pkbf(v2, v3);
            float l0 = v0 - __bfloat162float(__float2bfloat16(v0));
            float l1 = v1 - __bfloat162float(__float2bfloat16(v1));
            float l2 = v2 - __bfloat162float(__float2bfloat16(v2));
            float l3 = v3 - __bfloat162float(__float2bfloat16(v3));
            *(u32*)&hlo[nxt][br0][ic] = pkbf(l0, l1);
            *(u32*)&hlo[nxt][br1][ic] = pkbf(l2, l3);
            if (t == TT - 1) {
                hsfin[br0][ic] = v0; hsfin[br0][ic + 1] = v1;
                hsfin[br1][ic] = v2; hsfin[br1][ic + 1] = v3;
            }
        }
        __syncthreads();
        cur ^= 1;
    }

    // --- head: out[b,c] = sum_j hT[b,j]*w_head[c,j] + b_head[c] (fp32) ---
    if (tid < NB * CC) {
        const int b = tid / CC, c = tid % CC;
        const float* hf = hsfin[b];
        float s = b_head[c];
#pragma unroll
        for (int j = 0; j < HH; j++)
            s = fmaf(hf[j], w_head[c * HH + j], s);
        out[(size_t)(gb0 + b) * CC + c] = s;
    }
}

extern "C" void kernel_launch(void* const* d_in, const int* in_sizes, int n_in,
                              void* d_out, int out_size)
{
    (void)in_sizes; (void)n_in; (void)out_size;
    const float* x      = (const float*)d_in[0];
    const float* w_ih   = (const float*)d_in[1];
    const float* b_ih   = (const float*)d_in[2];
    const float* w_hh   = (const float*)d_in[3];
    const float* b_hh   = (const float*)d_in[4];
    const float* w_head = (const float*)d_in[5];
    const float* b_head = (const float*)d_in[6];
    float* out = (float*)d_out;

    rnn_hmma_kernel<<<BB / NB, NTHREADS>>>(
        x, w_ih, b_ih, w_hh, b_hh, w_head, b_head, out);
}

// round 12
// speedup vs baseline: 2.2672x; 1.2931x over previous
#include <cuda_runtime.h>
#include <cuda_bf16.h>
#include <cstdint>

// RNN: B=4096, T=1024, H=64, scalar input, C=5 head.
//   h_{t+1}[b,i] = tanh(x[b,t]*w_ih[i] + b_ih[i] + b_hh[i] + sum_j h_t[b,j]*w_hh[i,j])
//   out[b,c]     = sum_j hT[b,j]*w_head[c,j] + b_head[c]
//
// R11 = R10 (HMMA bf16-split, 644us) + decoupled batch-halves:
// warps 0-3 (batches 0-15) and warps 4-7 (batches 16-31) are fully
// independent -> replace the CTA-wide __syncthreads with per-half named
// barriers (bar.sync id,128), stage x per half, and anti-phase the halves
// with a skew preamble. Each SMSP hosts one warp of each half, so one
// half's serial tail (tanh/STS/barrier) overlaps the other's HMMA work.

#define BB 4096
#define TT 1024
#define HH 64
#define CC 5
#define NB 32
#define NTHREADS 256
#define HSTR 72            // bf16 elems per h row = 144 B
#define SKEW_FMA 160       // dependent FFMA chain for half 1, ~640 cyc

typedef uint32_t u32;

__device__ __forceinline__ u32 smem_u32(const void* p) {
    u32 a;
    asm("{ .reg .u64 t; cvta.to.shared.u64 t, %1; cvt.u32.u64 %0, t; }"
        : "=r"(a) : "l"(p));
    return a;
}
__device__ __forceinline__ u32 pkbf(float a, float b) {
    __nv_bfloat162 t = __floats2bfloat162_rn(a, b);
    return *reinterpret_cast<u32*>(&t);
}
__device__ __forceinline__ float ftanh(float xv) {
    // tanh(x) = 1 - 2/(e^{2x}+1); exact at saturation via inf.
    float e = __expf(2.0f * xv);
    return 1.0f - __fdividef(2.0f, e + 1.0f);
}
__device__ __forceinline__ void ldm4(u32* r, u32 addr) {
    asm volatile("ldmatrix.sync.aligned.m8n8.x4.shared.b16 {%0,%1,%2,%3}, [%4];"
                 : "=r"(r[0]), "=r"(r[1]), "=r"(r[2]), "=r"(r[3]) : "r"(addr));
}
__device__ __forceinline__ void mma16816(float* d, const u32* a, const u32* b) {
    asm volatile(
        "mma.sync.aligned.m16n8k16.row.col.f32.bf16.bf16.f32 "
        "{%0,%1,%2,%3}, {%4,%5,%6,%7}, {%8,%9}, {%0,%1,%2,%3};"
        : "+f"(d[0]), "+f"(d[1]), "+f"(d[2]), "+f"(d[3])
        : "r"(a[0]), "r"(a[1]), "r"(a[2]), "r"(a[3]), "r"(b[0]), "r"(b[1]));
}
__device__ __forceinline__ void bar_half(int mt) {
    asm volatile("bar.sync %0, 128;" :: "r"(1 + mt) : "memory");
}

extern "C" __global__ void __launch_bounds__(NTHREADS, 1)
rnn_hmma2_kernel(const float* __restrict__ x,
                 const float* __restrict__ w_ih,
                 const float* __restrict__ b_ih,
                 const float* __restrict__ w_hh,
                 const float* __restrict__ b_hh,
                 const float* __restrict__ w_head,
                 const float* __restrict__ b_head,
                 float* __restrict__ out)
{
    __shared__ __align__(16) __nv_bfloat16 hhi[2][NB][HSTR];  // 9216 B
    __shared__ __align__(16) __nv_bfloat16 hlo[2][NB][HSTR];  // 9216 B
    __shared__ float xs[32][NB];                              // 4096 B
    __shared__ float hsfin[NB][HH];                           // 8192 B

    const int tid  = threadIdx.x;
    const int lane = tid & 31;
    const int wrp  = tid >> 5;
    const int nt2  = wrp & 3;           // N-tile pair: i in [nt2*16, nt2*16+16)
    const int mt   = wrp >> 2;          // batch half: batches [mt*16, mt*16+16)
    const int gb0  = blockIdx.x * NB;
    const int tig  = lane & 3;          // thread-in-group
    const int gid  = lane >> 2;         // group id
    const int ht   = tid & 127;         // thread id within half

    // --- B fragments (W^T), loop-invariant, bf16 hi/lo split ---
    u32 bhi[2][4][2], blo[2][4][2];
#pragma unroll
    for (int nt = 0; nt < 2; nt++) {
        const int i = nt2 * 16 + nt * 8 + gid;
        const float* wr = w_hh + (size_t)i * HH;
#pragma unroll
        for (int ks = 0; ks < 4; ks++) {
            int j0 = ks * 16 + 2 * tig;
            float w0 = wr[j0],     w1 = wr[j0 + 1];
            float w2 = wr[j0 + 8], w3 = wr[j0 + 9];
            float h0 = __bfloat162float(__float2bfloat16(w0));
            float h1 = __bfloat162float(__float2bfloat16(w1));
            float h2 = __bfloat162float(__float2bfloat16(w2));
            float h3 = __bfloat162float(__float2bfloat16(w3));
            bhi[nt][ks][0] = pkbf(w0, w1);
            bhi[nt][ks][1] = pkbf(w2, w3);
            blo[nt][ks][0] = pkbf(w0 - h0, w1 - h1);
            blo[nt][ks][1] = pkbf(w2 - h2, w3 - h3);
        }
    }

    // --- per-lane epilogue constants ---
    float wihv[2][2], biasv[2][2];
#pragma unroll
    for (int nt = 0; nt < 2; nt++)
#pragma unroll
        for (int c = 0; c < 2; c++) {
            int i = nt2 * 16 + nt * 8 + 2 * tig + c;
            wihv[nt][c]  = w_ih[i];
            biasv[nt][c] = b_ih[i] + b_hh[i];
        }

    // --- zero h buffer 0 ---
    for (int e = tid; e < NB * HSTR / 2; e += NTHREADS) {
        ((u32*)hhi[0])[e] = 0u;
        ((u32*)hlo[0])[e] = 0u;
    }
    // --- stage x chunk 0 (per half) ---
    for (int e = ht; e < 16 * 32; e += 128) {
        int b = mt * 16 + (e >> 5), tcc = e & 31;
        xs[tcc][b] = x[(size_t)(gb0 + b) * TT + tcc];
    }

    const u32 hhi_a = smem_u32(hhi);
    const u32 hlo_a = smem_u32(hlo);
    const u32 aoff  = (u32)((mt * 16 + (lane & 15)) * 144 + ((lane >> 4) & 1) * 16);

    const int br0 = mt * 16 + gid;
    const int br1 = br0 + 8;

    __syncthreads();     // covers cross-half zero/stage init

    // --- anti-phase skew: half 1 burns ~640 cyc once (latency-bound chain) ---
    if (mt == 1) {
        float z = biasv[0][0] + 1.0f;
#pragma unroll
        for (int i = 0; i < SKEW_FMA; i++)
            asm volatile("fma.rn.f32 %0, %0, %1, %2;"
                         : "+f"(z) : "f"(0.9999999f), "f"(1e-30f));
        if (z == -123456.75f) xs[0][0] = z;   // defeat DCE, never true
    }

    int cur = 0;
    for (int t = 0; t < TT; t++) {
        const int tc = t & 31;
        if (tc == 0 && t > 0) {
            for (int e = ht; e < 16 * 32; e += 128) {
                int b = mt * 16 + (e >> 5), tcc = e & 31;
                xs[tcc][b] = x[(size_t)(gb0 + b) * TT + t + tcc];
            }
            bar_half(mt);
        }

        const u32 bufo = (u32)cur * (NB * HSTR * 2);

        // 6 independent depth-4 HMMA chains
        float dA[2][4] = {}, dB[2][4] = {}, dC[2][4] = {};
#pragma unroll
        for (int ks = 0; ks < 4; ks++) {
            u32 ahi[4], alo[4];
            ldm4(ahi, hhi_a + bufo + aoff + ks * 32);
            ldm4(alo, hlo_a + bufo + aoff + ks * 32);
            mma16816(dA[0], ahi, bhi[0][ks]);
            mma16816(dA[1], ahi, bhi[1][ks]);
            mma16816(dB[0], alo, bhi[0][ks]);
            mma16816(dB[1], alo, bhi[1][ks]);
            mma16816(dC[0], ahi, blo[0][ks]);
            mma16816(dC[1], ahi, blo[1][ks]);
        }

        // epilogue: combine, +x*w_ih+bias, tanh, split to bf16 hi/lo, store
        const float xv0 = xs[tc][br0];
        const float xv1 = xs[tc][br1];
        const int nxt = cur ^ 1;
#pragma unroll
        for (int nt = 0; nt < 2; nt++) {
            const int ic = nt2 * 16 + nt * 8 + 2 * tig;
            float s0 = dA[nt][0] + dB[nt][0] + dC[nt][0] + fmaf(xv0, wihv[nt][0], biasv[nt][0]);
            float s1 = dA[nt][1] + dB[nt][1] + dC[nt][1] + fmaf(xv0, wihv[nt][1], biasv[nt][1]);
            float s2 = dA[nt][2] + dB[nt][2] + dC[nt][2] + fmaf(xv1, wihv[nt][0], biasv[nt][0]);
            float s3 = dA[nt][3] + dB[nt][3] + dC[nt][3] + fmaf(xv1, wihv[nt][1], biasv[nt][1]);
            float v0 = ftanh(s0), v1 = ftanh(s1), v2 = ftanh(s2), v3 = ftanh(s3);
            *(u32*)&hhi[nxt][br0][ic] = pkbf(v0, v1);
            *(u32*)&hhi[nxt][br1][ic] = pkbf(v2, v3);
            float l0 = v0 - __bfloat162float(__float2bfloat16(v0));
            float l1 = v1 - __bfloat162float(__float2bfloat16(v1));
            float l2 = v2 - __bfloat162float(__float2bfloat16(v2));
            float l3 = v3 - __bfloat162float(__float2bfloat16(v3));
            *(u32*)&hlo[nxt][br0][ic] = pkbf(l0, l1);
            *(u32*)&hlo[nxt][br1][ic] = pkbf(l2, l3);
            if (t == TT - 1) {
                hsfin[br0][ic] = v0; hsfin[br0][ic + 1] = v1;
                hsfin[br1][ic] = v2; hsfin[br1][ic + 1] = v3;
            }
        }
        bar_half(mt);
        cur ^= 1;
    }

    __syncthreads();     // re-align halves before the head

    // --- head: out[b,c] = sum_j hT[b,j]*w_head[c,j] + b_head[c] (fp32) ---
    if (tid < NB * CC) {
        const int b = tid / CC, c = tid % CC;
        const float* hf = hsfin[b];
        float s = b_head[c];
#pragma unroll
        for (int j = 0; j < HH; j++)
            s = fmaf(hf[j], w_head[c * HH + j], s);
        out[(size_t)(gb0 + b) * CC + c] = s;
    }
}

extern "C" void kernel_launch(void* const* d_in, const int* in_sizes, int n_in,
                              void* d_out, int out_size)
{
    (void)in_sizes; (void)n_in; (void)out_size;
    const float* x      = (const float*)d_in[0];
    const float* w_ih   = (const float*)d_in[1];
    const float* b_ih   = (const float*)d_in[2];
    const float* w_hh   = (const float*)d_in[3];
    const float* b_hh   = (const float*)d_in[4];
    const float* w_head = (const float*)d_in[5];
    const float* b_head = (const float*)d_in[6];
    float* out = (float*)d_out;

    rnn_hmma2_kernel<<<BB / NB, NTHREADS>>>(
        x, w_ih, b_ih, w_hh, b_hh, w_head, b_head, out);
}